// round 3
// baseline (speedup 1.0000x reference)
#include <cuda_runtime.h>
#include <cuda_bf16.h>

// x:       (L=2048, B=16) int32   -> x[l*16 + b]
// embed_w: (V=50257, D=1024) fp32 -> w[t*1024 + d]
// out:     (B=16, D=1024, L=2048) fp32 -> out[b*D*L + d*L + l]
// rows with token >= 20 are zero; output scaled by sqrt(8).

#define L_DIM   2048
#define B_DIM   16
#define D_DIM   1024
#define MAXTOK  20
#define SCALE   2.8284271247461903f  // sqrt(8)

// Tiling: block = (l-tile 128) x (all 16 b) x (d-tile 16) = 8192 float4
// Grid = 16 l-tiles * 64 d-tiles = 1024 blocks (single wave on 148 SMs).
#define LTILE    128
#define LTILE4   32
#define DTILE    16
#define NLTILES  16
#define NDTILES  64
#define NBLOCKS  1024
#define TPB      256
#define ITERS    32     // 8192 float4 / 256 threads

__global__ void __launch_bounds__(TPB) fused_embed_kernel(
    const int* __restrict__ x,
    const float* __restrict__ w,
    float4* __restrict__ out)
{
    __shared__ int tok[LTILE * B_DIM];   // 2048 tokens, natural [l_loc*16 + b]
    __shared__ int anyhit;

    const int tid = threadIdx.x;
    const int lt  = blockIdx.x & (NLTILES - 1);
    const int dt  = blockIdx.x >> 4;

    if (tid == 0) anyhit = 0;
    __syncthreads();

    // Coalesced token stage: 2048 ints = 512 int4, 2 per thread.
    const int4* xsrc = (const int4*)(x + lt * LTILE * B_DIM);
    int local = 0;
    #pragma unroll
    for (int k = 0; k < 2; k++) {
        int4 v = __ldg(xsrc + k * TPB + tid);
        ((int4*)tok)[k * TPB + tid] = v;
        local |= (v.x < MAXTOK) | (v.y < MAXTOK) | (v.z < MAXTOK) | (v.w < MAXTOK);
    }
    if (local) anyhit = 1;
    __syncthreads();

    // i -> (d_loc, b, l4_loc): lanes get consecutive l4 -> 512B coalesced stores
    if (!anyhit) {
        const float4 z = make_float4(0.f, 0.f, 0.f, 0.f);
        #pragma unroll
        for (int it = 0; it < ITERS; it++) {
            int i    = it * TPB + tid;
            int l4   = i & (LTILE4 - 1);
            int b    = (i >> 5) & (B_DIM - 1);
            int dl   = i >> 9;
            size_t idx = ((size_t)b * D_DIM + dt * DTILE + dl) * (L_DIM / 4)
                       + lt * LTILE4 + l4;
            __stcs(out + idx, z);
        }
    } else {
        // Rare path: ~13 of 1024 blocks ever take this.
        #pragma unroll 4
        for (int it = 0; it < ITERS; it++) {
            int i    = it * TPB + tid;
            int l4   = i & (LTILE4 - 1);
            int b    = (i >> 5) & (B_DIM - 1);
            int dl   = i >> 9;
            int d    = dt * DTILE + dl;
            int l0   = l4 << 2;   // l_loc of first of 4

            int t0 = tok[(l0 + 0) * B_DIM + b];
            int t1 = tok[(l0 + 1) * B_DIM + b];
            int t2 = tok[(l0 + 2) * B_DIM + b];
            int t3 = tok[(l0 + 3) * B_DIM + b];

            float4 v;
            v.x = (t0 < MAXTOK) ? __ldg(w + (size_t)t0 * D_DIM + d) * SCALE : 0.0f;
            v.y = (t1 < MAXTOK) ? __ldg(w + (size_t)t1 * D_DIM + d) * SCALE : 0.0f;
            v.z = (t2 < MAXTOK) ? __ldg(w + (size_t)t2 * D_DIM + d) * SCALE : 0.0f;
            v.w = (t3 < MAXTOK) ? __ldg(w + (size_t)t3 * D_DIM + d) * SCALE : 0.0f;

            size_t idx = ((size_t)b * D_DIM + d) * (L_DIM / 4)
                       + lt * LTILE4 + l4;
            __stcs(out + idx, v);
        }
    }
}

extern "C" void kernel_launch(void* const* d_in, const int* in_sizes, int n_in,
                              void* d_out, int out_size)
{
    const int*   x = (const int*)d_in[0];
    const float* w = (const float*)d_in[1];
    fused_embed_kernel<<<NBLOCKS, TPB>>>(x, w, (float4*)d_out);
}

// round 4
// speedup vs baseline: 3.9722x; 3.9722x over previous
#include <cuda_runtime.h>
#include <cuda_bf16.h>

// x:       (L=2048, B=16) int32   -> x[l*16 + b]
// embed_w: (V=50257, D=1024) fp32 -> w[t*1024 + d]
// out:     (B=16, D=1024, L=2048) fp32 -> out[b*D*L + d*L + l]
// rows with token >= 20 are zero; output scaled by sqrt(8).

#define L_DIM   2048
#define B_DIM   16
#define D_DIM   1024
#define MAXTOK  20
#define SCALE   2.8284271247461903f  // sqrt(8)

#define TOTAL4  8388608   // 16*1024*2048 / 4  float4 elements
#define NPOS    32768     // L*B token positions

// ---------------------------------------------------------------------------
// Kernel 1: zero-fill output. Pure streaming stores, no loads.
// Grid-wide sequential sweep: warp-, block-, and iteration-contiguous.
// Measured ~7.2 TB/s (at the LTS/HBM write ceiling). DO NOT change pattern.
// ---------------------------------------------------------------------------
#define ZBLOCKS 4096
#define ZTPB    256
#define ZITER   8   // 4096*256*8 = 8388608

__global__ void __launch_bounds__(ZTPB) zero_fill_kernel(float4* __restrict__ out)
{
    const float4 z = make_float4(0.f, 0.f, 0.f, 0.f);
    unsigned idx = blockIdx.x * ZTPB + threadIdx.x;
    const unsigned stride = ZBLOCKS * ZTPB;  // 1048576
    #pragma unroll
    for (int k = 0; k < ZITER; k++) {
        __stcs(out + idx, z);
        idx += stride;
    }
}

// ---------------------------------------------------------------------------
// Kernel 2: scatter rare nonzero rows. ONE THREAD per (l,b) position
// (32768 threads total, vs 1M in the old version). Hits are compacted into
// a smem list, then the whole block writes each hit row cooperatively.
// ---------------------------------------------------------------------------
#define STPB     256
#define SBLOCKS  (NPOS / STPB)   // 128

__global__ void __launch_bounds__(STPB) scatter_kernel(
    const int* __restrict__ x,
    const float* __restrict__ w,
    float* __restrict__ out)
{
    __shared__ int hit_pos[STPB];   // worst case: every position hits
    __shared__ int hit_tok[STPB];
    __shared__ int nhit;

    const int tid = threadIdx.x;
    if (tid == 0) nhit = 0;
    __syncthreads();

    int pos = blockIdx.x * STPB + tid;      // fully coalesced 1 KiB per block
    int t = __ldg(x + pos);
    if (t < MAXTOK) {
        int slot = atomicAdd(&nhit, 1);
        hit_pos[slot] = pos;
        hit_tok[slot] = t;
    }
    __syncthreads();

    int n = nhit;
    for (int h = 0; h < n; h++) {           // ~0.1 hits per block on average
        int p = hit_pos[h];
        int t2 = hit_tok[h];
        int l = p >> 4;                     // p = l*16 + b
        int b = p & 15;
        const float* wrow = w + (size_t)t2 * D_DIM;
        float* obase = out + ((size_t)b * D_DIM * L_DIM) + l;
        #pragma unroll 4
        for (int d = tid; d < D_DIM; d += STPB) {
            obase[(size_t)d * L_DIM] = __ldg(wrow + d) * SCALE;
        }
    }
}

// ---------------------------------------------------------------------------
extern "C" void kernel_launch(void* const* d_in, const int* in_sizes, int n_in,
                              void* d_out, int out_size)
{
    const int*   x = (const int*)d_in[0];
    const float* w = (const float*)d_in[1];

    zero_fill_kernel<<<ZBLOCKS, ZTPB>>>((float4*)d_out);
    scatter_kernel<<<SBLOCKS, STPB>>>(x, w, (float*)d_out);
}